// round 8
// baseline (speedup 1.0000x reference)
#include <cuda_runtime.h>
#include <cuda_bf16.h>
#include <cstdint>

// ---------------------------------------------------------------------------
// Problem constants
// ---------------------------------------------------------------------------
#define B_   16
#define C_   306
#define CP_  320      // C padded to multiple of 32
#define T_   4000
#define M_   128
#define TN_  128      // t-tile per CTA
#define KC_  32       // K chunk
#define NCHUNK 10     // CP_/KC_

#define INV0 50.0f
#define INV1 12.5f
#define INV2 3.125f

// smem tile row stride in bytes (64B data + 16B pad -> conflict-free ldmatrix)
#define RS 80

// SMEM layout (bytes, dynamic)
#define OFF_A(s, tile) ((s) * 20480 + (tile) * 10240)
#define OFF_X(s) (61440 + (s) * 16384)
#define OFF_B(s, tile) (94208 + (s) * 20480 + (tile) * 10240)
#define SMEM_TOTAL 135168

#define NTHREADS 384   // 8 consumer warps + 4 producer warps

// Scratch: channel weights as split bf16, layout [b][m][c] (c contiguous, padded)
__device__ __align__(16) __nv_bfloat16 g_w_hi[B_ * M_ * CP_];
__device__ __align__(16) __nv_bfloat16 g_w_lo[B_ * M_ * CP_];

__device__ __forceinline__ uint32_t smem_u32(const void* p) {
    uint32_t a;
    asm("{ .reg .u64 t; cvta.to.shared.u64 t, %1; cvt.u32.u64 %0, t; }" : "=r"(a) : "l"(p));
    return a;
}

#define LDSM4(r, addr) \
    asm volatile("ldmatrix.sync.aligned.m8n8.x4.shared.b16 {%0,%1,%2,%3}, [%4];" \
        : "=r"((r)[0]), "=r"((r)[1]), "=r"((r)[2]), "=r"((r)[3]) : "r"(addr))

#define STS16(addr, v) \
    asm volatile("st.shared.v4.b32 [%0], {%1,%2,%3,%4};" \
        :: "r"(addr), "r"((v).x), "r"((v).y), "r"((v).z), "r"((v).w) : "memory")

#define CP16(dst, src, sz) \
    asm volatile("cp.async.cg.shared.global [%0], [%1], 16, %2;" \
        :: "r"(dst), "l"(src), "r"(sz) : "memory")

#define CP_COMMIT() asm volatile("cp.async.commit_group;" ::: "memory")

// Producer-only barrier (cross-thread cp.async visibility before convert).
#define PROD_BAR() asm volatile("bar.sync 1, 128;" ::: "memory")

#define MMA_BF16(c, a, b0, b1) \
    asm volatile("mma.sync.aligned.m16n8k16.row.col.f32.bf16.bf16.f32 " \
        "{%0,%1,%2,%3}, {%4,%5,%6,%7}, {%8,%9}, {%0,%1,%2,%3};" \
        : "+f"((c)[0]), "+f"((c)[1]), "+f"((c)[2]), "+f"((c)[3]) \
        : "r"((a)[0]), "r"((a)[1]), "r"((a)[2]), "r"((a)[3]), "r"(b0), "r"(b1))

// ---------------------------------------------------------------------------
// Kernel 1: gate weights -> normalized -> split bf16 -> g_w_hi/lo [b][m][c]
// ---------------------------------------------------------------------------
__global__ void __launch_bounds__(CP_) mrm_weights_kernel(
    const float* __restrict__ pos, const float* __restrict__ tpos,
    const float* __restrict__ w1, const float* __restrict__ b1,
    const float* __restrict__ w2, const float* __restrict__ b2)
{
    __shared__ float s_w1[96], s_b1[32], s_w2[32];
    __shared__ float warp_sums[10];
    __shared__ float s_total;

    const int bm = blockIdx.x;
    const int b = bm / M_, m = bm % M_;
    const int tid = threadIdx.x;

    if (tid < 96) s_w1[tid] = w1[tid];
    else if (tid < 128) s_b1[tid - 96] = b1[tid - 96];
    else if (tid < 160) s_w2[tid - 128] = w2[tid - 128];
    __syncthreads();

    const float txp = tpos[2 * m], typ = tpos[2 * m + 1];
    const float bias2 = b2[0];

    float wv = 0.0f;
    const int c = tid;
    if (c < C_) {
        const float px = pos[((size_t)b * C_ + c) * 2 + 0];
        const float py = pos[((size_t)b * C_ + c) * 2 + 1];
        const float dx = px - txp, dy = py - typ;
        const float d2 = dx * dx + dy * dy;
        const float s0 = __expf(-d2 * INV0);
        const float s1 = __expf(-d2 * INV1);
        const float s2 = __expf(-d2 * INV2);
        float acc = bias2;
#pragma unroll
        for (int j = 0; j < 32; j++) {
            float h = s_b1[j];
            h = fmaf(s0, s_w1[j], h);
            h = fmaf(s1, s_w1[32 + j], h);
            h = fmaf(s2, s_w1[64 + j], h);
            h = fmaxf(h, 0.0f);
            acc = fmaf(h, s_w2[j], acc);
        }
        wv = acc;
    }

    float v = wv;
#pragma unroll
    for (int o = 16; o > 0; o >>= 1) v += __shfl_down_sync(0xffffffffu, v, o);
    if ((tid & 31) == 0) warp_sums[tid >> 5] = v;
    __syncthreads();
    if (tid == 0) {
        float s = 0.0f;
#pragma unroll
        for (int i = 0; i < 10; i++) s += warp_sums[i];
        s_total = s + 1e-8f;
    }
    __syncthreads();

    float wn = (c < C_) ? (wv / s_total) : 0.0f;
    __nv_bfloat16 h = __float2bfloat16(wn);
    __nv_bfloat16 l = __float2bfloat16(wn - __bfloat162float(h));
    const size_t o = ((size_t)b * M_ + m) * CP_ + c;
    g_w_hi[o] = h;
    g_w_lo[o] = l;
}

// ---------------------------------------------------------------------------
// Kernel 2: warp-specialized split-bf16 HMMA GEMM.
// MMA ordering: all 16 independent hh, then 16 hl, then 16 lh — no
// back-to-back RAW on accumulators (the R4/R7 tensor-pipe limiter).
// ---------------------------------------------------------------------------
__global__ void __launch_bounds__(NTHREADS, 1) mrm_hmma_kernel(
    const float* __restrict__ x, float* __restrict__ out)
{
    extern __shared__ __align__(16) char smem[];
    const uint32_t sb = smem_u32(smem);

    const int b   = blockIdx.y;
    const int t0  = blockIdx.x * TN_;
    const int tid = threadIdx.x;
    const int lane = tid & 31;
    const bool is_producer = (tid >= 256);

    const float* xb = x + (size_t)b * C_ * T_;
    const char* xrow_base = (const char*)(xb) + (size_t)t0 * 4;
    const __nv_bfloat16* gwh = g_w_hi + (size_t)b * M_ * CP_;
    const __nv_bfloat16* gwl = g_w_lo + (size_t)b * M_ * CP_;

    // ---------------- producer helpers ----------------
    const int ptid = tid - 256;

    auto issue_chunk = [&](int chunk) {
        const int k0 = chunk * KC_;
        const int as = chunk % 3;
        const int xs = chunk & 1;
#pragma unroll
        for (int r = 0; r < 8; r++) {
            const int c = ptid + r * 128;
            const int tile = c >> 9;
            const int idx  = c & 511;
            const int row  = idx >> 2;
            const int j    = idx & 3;
            const __nv_bfloat16* src = (tile ? gwl : gwh) + (size_t)row * CP_ + k0 + j * 8;
            const uint32_t dst = sb + OFF_A(as, tile) + row * RS + j * 16;
            CP16(dst, src, 16);
        }
#pragma unroll
        for (int r = 0; r < 8; r++) {
            const int c = ptid + r * 128;
            const int k = c >> 5;
            const int j = c & 31;
            const char* src = xrow_base + (size_t)(k0 + k) * (T_ * 4) + j * 16;
            const uint32_t dst = sb + OFF_X(xs) + k * 512 + j * 16;
            const uint32_t sz = ((k0 + k) < C_ && (t0 + j * 4) < T_) ? 16u : 0u;
            CP16(dst, src, sz);
        }
        CP_COMMIT();
    };

    auto convert_chunk = [&](int chunk) {
        const int k0 = chunk * KC_;
        const int s  = chunk & 1;
        const int tl = ptid;
        const uint32_t xbase = sb + OFF_X(s) + tl * 4;
        float v[32];
#pragma unroll
        for (int k = 0; k < 32; k++) {
            float f;
            asm volatile("ld.shared.f32 %0, [%1];" : "=f"(f) : "r"(xbase + k * 512));
            v[k] = ((k0 + k) < C_) ? f : 0.0f;
        }
        uint32_t hi[16], lo[16];
#pragma unroll
        for (int q = 0; q < 16; q++) {
            float v0 = v[2 * q], v1 = v[2 * q + 1];
            __nv_bfloat16 h0 = __float2bfloat16(v0);
            __nv_bfloat16 h1 = __float2bfloat16(v1);
            float l0 = v0 - __bfloat162float(h0);
            float l1 = v1 - __bfloat162float(h1);
            hi[q] = (uint32_t)__bfloat16_as_ushort(h0)
                  | ((uint32_t)__bfloat16_as_ushort(h1) << 16);
            __nv_bfloat16 g0 = __float2bfloat16(l0);
            __nv_bfloat16 g1 = __float2bfloat16(l1);
            lo[q] = (uint32_t)__bfloat16_as_ushort(g0)
                  | ((uint32_t)__bfloat16_as_ushort(g1) << 16);
        }
        const uint32_t bh = sb + OFF_B(s, 0) + tl * RS;
        const uint32_t bl = sb + OFF_B(s, 1) + tl * RS;
#pragma unroll
        for (int q4 = 0; q4 < 4; q4++) {
            uint4 vh = make_uint4(hi[4*q4], hi[4*q4+1], hi[4*q4+2], hi[4*q4+3]);
            uint4 vl = make_uint4(lo[4*q4], lo[4*q4+1], lo[4*q4+2], lo[4*q4+3]);
            STS16(bh + q4 * 16, vh);
            STS16(bl + q4 * 16, vl);
        }
    };

    // ---------------- consumer setup ----------------
    const int wid = tid >> 5;
    const int warp_m = wid >> 2;        // 0..1
    const int warp_n = wid & 3;         // 0..3

    const int lr  = lane & 7;
    const int sel = lane >> 3;
    const int a_row = warp_m * 64 + lr + (sel & 1) * 8;
    const int a_col = (sel >> 1) * 16;
    const int b_row = warp_n * 32 + lr + (sel >> 1) * 8;
    const int b_col = (sel & 1) * 16;

    float acc[4][4][4];
#pragma unroll
    for (int i = 0; i < 4; i++)
#pragma unroll
        for (int j = 0; j < 4; j++)
#pragma unroll
            for (int q = 0; q < 4; q++) acc[i][j][q] = 0.0f;

    // ---------------- prologue ----------------
    if (is_producer) {
        issue_chunk(0);
        issue_chunk(1);
        asm volatile("cp.async.wait_group 1;" ::: "memory");
        PROD_BAR();
        convert_chunk(0);
    }
    __syncthreads();

    // ---------------- main loop ----------------
    for (int i = 0; i < NCHUNK; i++) {
        if (is_producer) {
            if (i + 2 < NCHUNK) issue_chunk(i + 2);
            if (i + 1 < NCHUNK) {
                if (i + 2 < NCHUNK) asm volatile("cp.async.wait_group 1;" ::: "memory");
                else                asm volatile("cp.async.wait_group 0;" ::: "memory");
                PROD_BAR();
                convert_chunk(i + 1);
            }
        } else {
            const uint32_t sAh = sb + OFF_A(i % 3, 0);
            const uint32_t sAl = sb + OFF_A(i % 3, 1);
            const uint32_t sBh = sb + OFF_B(i & 1, 0);
            const uint32_t sBl = sb + OFF_B(i & 1, 1);
#pragma unroll
            for (int ks = 0; ks < 2; ks++) {
                uint32_t af[4][4], al[4][4], bh[2][4], bl[2][4];
                const uint32_t acol = ks * 32 + a_col;
                const uint32_t bcol = ks * 32 + b_col;
#pragma unroll
                for (int g = 0; g < 2; g++) {
                    LDSM4(bh[g], sBh + (uint32_t)(b_row + g * 16) * RS + bcol);
                    LDSM4(bl[g], sBl + (uint32_t)(b_row + g * 16) * RS + bcol);
                }
#pragma unroll
                for (int mf = 0; mf < 4; mf++)
                    LDSM4(af[mf], sAh + (uint32_t)(a_row + mf * 16) * RS + acol);
#pragma unroll
                for (int mf = 0; mf < 4; mf++)
                    LDSM4(al[mf], sAl + (uint32_t)(a_row + mf * 16) * RS + acol);

                // pass 1: 16 independent hi*hi
#pragma unroll
                for (int mf = 0; mf < 4; mf++)
#pragma unroll
                    for (int nf = 0; nf < 4; nf++) {
                        const int g = nf >> 1, s2 = (nf & 1) * 2;
                        MMA_BF16(acc[mf][nf], af[mf], bh[g][s2], bh[g][s2 + 1]);
                    }
                // pass 2: 16 hi*lo (dependency 16 instructions upstream)
#pragma unroll
                for (int mf = 0; mf < 4; mf++)
#pragma unroll
                    for (int nf = 0; nf < 4; nf++) {
                        const int g = nf >> 1, s2 = (nf & 1) * 2;
                        MMA_BF16(acc[mf][nf], af[mf], bl[g][s2], bl[g][s2 + 1]);
                    }
                // pass 3: 16 lo*hi
#pragma unroll
                for (int mf = 0; mf < 4; mf++)
#pragma unroll
                    for (int nf = 0; nf < 4; nf++) {
                        const int g = nf >> 1, s2 = (nf & 1) * 2;
                        MMA_BF16(acc[mf][nf], al[mf], bh[g][s2], bh[g][s2 + 1]);
                    }
            }
        }
        __syncthreads();
    }

    // ---------------- epilogue (consumers only) ----------------
    if (!is_producer && (t0 + warp_n * 32 < T_)) {
        const int mb = warp_m * 64 + (lane >> 2);
        const int cb = t0 + warp_n * 32 + (lane & 3) * 2;
#pragma unroll
        for (int mf = 0; mf < 4; mf++) {
#pragma unroll
            for (int nf = 0; nf < 4; nf++) {
                const int m = mb + mf * 16;
                const int t = cb + nf * 8;
                float* o0 = out + ((size_t)b * M_ + m) * T_ + t;
                float* o1 = out + ((size_t)b * M_ + m + 8) * T_ + t;
                *(float2*)o0 = make_float2(acc[mf][nf][0], acc[mf][nf][1]);
                *(float2*)o1 = make_float2(acc[mf][nf][2], acc[mf][nf][3]);
            }
        }
    }
}

// ---------------------------------------------------------------------------
extern "C" void kernel_launch(void* const* d_in, const int* in_sizes, int n_in,
                              void* d_out, int out_size) {
    const float* x    = (const float*)d_in[0];
    const float* pos  = (const float*)d_in[1];
    const float* tpos = (const float*)d_in[2];
    const float* w1   = (const float*)d_in[3];
    const float* b1   = (const float*)d_in[4];
    const float* w2   = (const float*)d_in[5];
    const float* b2   = (const float*)d_in[6];
    float* out = (float*)d_out;

    cudaFuncSetAttribute(mrm_hmma_kernel,
                         cudaFuncAttributeMaxDynamicSharedMemorySize, SMEM_TOTAL);

    mrm_weights_kernel<<<B_ * M_, CP_>>>(pos, tpos, w1, b1, w2, b2);

    dim3 grid((T_ + TN_ - 1) / TN_, B_);   // 32 x 16 = 512 CTAs
    mrm_hmma_kernel<<<grid, NTHREADS, SMEM_TOTAL>>>(x, out);
}

// round 9
// speedup vs baseline: 1.3359x; 1.3359x over previous
#include <cuda_runtime.h>
#include <cuda_fp16.h>
#include <cstdint>

// ---------------------------------------------------------------------------
// Problem constants
// ---------------------------------------------------------------------------
#define B_   16
#define C_   306
#define CP_  320      // C padded to multiple of 32
#define T_   4000
#define M_   128
#define TN_  128      // t-tile per CTA
#define KC_  32       // K chunk
#define NCHUNK 10     // CP_/KC_

#define INV0 50.0f
#define INV1 12.5f
#define INV2 3.125f

// smem tile row stride in bytes (64B data + 16B pad -> conflict-free ldmatrix)
#define RS 80

// SMEM layout (bytes, dynamic) — single fp16 tiles
// A: 3 stages x 10240
#define OFF_A(s)  ((s) * 10240)
// X fp32 staging: 2 stages x 16384
#define OFF_X(s)  (30720 + (s) * 16384)
// B: 2 stages x 10240
#define OFF_B(s)  (63488 + (s) * 10240)
#define SMEM_TOTAL 83968

#define NTHREADS 384   // 8 consumer warps + 4 producer warps

// Scratch: normalized channel weights, fp16, layout [b][m][c] (padded)
__device__ __align__(16) __half g_w[B_ * M_ * CP_];

__device__ __forceinline__ uint32_t smem_u32(const void* p) {
    uint32_t a;
    asm("{ .reg .u64 t; cvta.to.shared.u64 t, %1; cvt.u32.u64 %0, t; }" : "=r"(a) : "l"(p));
    return a;
}

#define LDSM4(r, addr) \
    asm volatile("ldmatrix.sync.aligned.m8n8.x4.shared.b16 {%0,%1,%2,%3}, [%4];" \
        : "=r"((r)[0]), "=r"((r)[1]), "=r"((r)[2]), "=r"((r)[3]) : "r"(addr))

#define STS16(addr, v) \
    asm volatile("st.shared.v4.b32 [%0], {%1,%2,%3,%4};" \
        :: "r"(addr), "r"((v).x), "r"((v).y), "r"((v).z), "r"((v).w) : "memory")

#define CP16(dst, src, sz) \
    asm volatile("cp.async.cg.shared.global [%0], [%1], 16, %2;" \
        :: "r"(dst), "l"(src), "r"(sz) : "memory")

#define CP_COMMIT() asm volatile("cp.async.commit_group;" ::: "memory")

// Producer-only barrier (cross-thread cp.async visibility before convert).
#define PROD_BAR() asm volatile("bar.sync 1, 128;" ::: "memory")

#define MMA_F16(c, a, b0, b1) \
    asm volatile("mma.sync.aligned.m16n8k16.row.col.f32.f16.f16.f32 " \
        "{%0,%1,%2,%3}, {%4,%5,%6,%7}, {%8,%9}, {%0,%1,%2,%3};" \
        : "+f"((c)[0]), "+f"((c)[1]), "+f"((c)[2]), "+f"((c)[3]) \
        : "r"((a)[0]), "r"((a)[1]), "r"((a)[2]), "r"((a)[3]), "r"(b0), "r"(b1))

// ---------------------------------------------------------------------------
// Kernel 1: gate weights -> normalized -> fp16 -> g_w [b][m][c]
// ---------------------------------------------------------------------------
__global__ void __launch_bounds__(CP_) mrm_weights_kernel(
    const float* __restrict__ pos, const float* __restrict__ tpos,
    const float* __restrict__ w1, const float* __restrict__ b1,
    const float* __restrict__ w2, const float* __restrict__ b2)
{
    __shared__ float s_w1[96], s_b1[32], s_w2[32];
    __shared__ float warp_sums[10];
    __shared__ float s_total;

    const int bm = blockIdx.x;
    const int b = bm / M_, m = bm % M_;
    const int tid = threadIdx.x;

    if (tid < 96) s_w1[tid] = w1[tid];
    else if (tid < 128) s_b1[tid - 96] = b1[tid - 96];
    else if (tid < 160) s_w2[tid - 128] = w2[tid - 128];
    __syncthreads();

    const float txp = tpos[2 * m], typ = tpos[2 * m + 1];
    const float bias2 = b2[0];

    float wv = 0.0f;
    const int c = tid;
    if (c < C_) {
        const float px = pos[((size_t)b * C_ + c) * 2 + 0];
        const float py = pos[((size_t)b * C_ + c) * 2 + 1];
        const float dx = px - txp, dy = py - typ;
        const float d2 = dx * dx + dy * dy;
        const float s0 = __expf(-d2 * INV0);
        const float s1 = __expf(-d2 * INV1);
        const float s2 = __expf(-d2 * INV2);
        float acc = bias2;
#pragma unroll
        for (int j = 0; j < 32; j++) {
            float h = s_b1[j];
            h = fmaf(s0, s_w1[j], h);
            h = fmaf(s1, s_w1[32 + j], h);
            h = fmaf(s2, s_w1[64 + j], h);
            h = fmaxf(h, 0.0f);
            acc = fmaf(h, s_w2[j], acc);
        }
        wv = acc;
    }

    float v = wv;
#pragma unroll
    for (int o = 16; o > 0; o >>= 1) v += __shfl_down_sync(0xffffffffu, v, o);
    if ((tid & 31) == 0) warp_sums[tid >> 5] = v;
    __syncthreads();
    if (tid == 0) {
        float s = 0.0f;
#pragma unroll
        for (int i = 0; i < 10; i++) s += warp_sums[i];
        s_total = s + 1e-8f;
    }
    __syncthreads();

    float wn = (c < C_) ? (wv / s_total) : 0.0f;   // padding rows get 0
    g_w[((size_t)b * M_ + m) * CP_ + c] = __float2half(wn);
}

// ---------------------------------------------------------------------------
// Kernel 2: warp-specialized single-fp16 HMMA GEMM, 2 CTAs/SM.
// 8 consumer warps (2(m) x 4(n), warp tile 64x32), 4 producer warps.
// ---------------------------------------------------------------------------
__global__ void __launch_bounds__(NTHREADS, 2) mrm_hmma_kernel(
    const float* __restrict__ x, float* __restrict__ out)
{
    extern __shared__ __align__(16) char smem[];
    const uint32_t sb = smem_u32(smem);

    const int b   = blockIdx.y;
    const int t0  = blockIdx.x * TN_;
    const int tid = threadIdx.x;
    const int lane = tid & 31;
    const bool is_producer = (tid >= 256);

    const float* xb = x + (size_t)b * C_ * T_;
    const char* xrow_base = (const char*)(xb) + (size_t)t0 * 4;
    const __half* gw = g_w + (size_t)b * M_ * CP_;

    // ---------------- producer helpers ----------------
    const int ptid = tid - 256;                 // 0..127

    auto issue_chunk = [&](int chunk) {
        const int k0 = chunk * KC_;
        const int as = chunk % 3;
        const int xs = chunk & 1;
        // A tile: 128 rows x 64B = 512 x 16B chunks, 4 per thread
#pragma unroll
        for (int r = 0; r < 4; r++) {
            const int c = ptid + r * 128;
            const int row = c >> 2;
            const int j   = c & 3;
            const __half* src = gw + (size_t)row * CP_ + k0 + j * 8;
            const uint32_t dst = sb + OFF_A(as) + row * RS + j * 16;
            CP16(dst, src, 16);
        }
        // X staging: 32 k-rows x 512B = 1024 x 16B chunks, 8 per thread
#pragma unroll
        for (int r = 0; r < 8; r++) {
            const int c = ptid + r * 128;
            const int k = c >> 5;
            const int j = c & 31;
            const char* src = xrow_base + (size_t)(k0 + k) * (T_ * 4) + j * 16;
            const uint32_t dst = sb + OFF_X(xs) + k * 512 + j * 16;
            const uint32_t sz = ((k0 + k) < C_ && (t0 + j * 4) < T_) ? 16u : 0u;
            CP16(dst, src, sz);
        }
        CP_COMMIT();
    };

    auto convert_chunk = [&](int chunk) {
        const int k0 = chunk * KC_;
        const int s  = chunk & 1;
        const int tl = ptid;                    // t column 0..127
        const uint32_t xbase = sb + OFF_X(s) + tl * 4;
        float v[32];
#pragma unroll
        for (int k = 0; k < 32; k++) {
            float f;
            asm volatile("ld.shared.f32 %0, [%1];" : "=f"(f) : "r"(xbase + k * 512));
            v[k] = ((k0 + k) < C_) ? f : 0.0f;  // kill K-padding garbage
        }
        uint32_t hp[16];
#pragma unroll
        for (int q = 0; q < 16; q++) {
            __half h0 = __float2half(v[2 * q]);
            __half h1 = __float2half(v[2 * q + 1]);
            hp[q] = (uint32_t)__half_as_ushort(h0)
                  | ((uint32_t)__half_as_ushort(h1) << 16);
        }
        const uint32_t bbase = sb + OFF_B(s) + tl * RS;
#pragma unroll
        for (int q4 = 0; q4 < 4; q4++) {
            uint4 vh = make_uint4(hp[4*q4], hp[4*q4+1], hp[4*q4+2], hp[4*q4+3]);
            STS16(bbase + q4 * 16, vh);
        }
    };

    // ---------------- consumer setup ----------------
    const int wid = tid >> 5;
    const int warp_m = wid >> 2;        // 0..1
    const int warp_n = wid & 3;         // 0..3

    const int lr  = lane & 7;
    const int sel = lane >> 3;          // 0..3
    const int a_row = warp_m * 64 + lr + (sel & 1) * 8;
    const int a_col = (sel >> 1) * 16;
    const int b_row = warp_n * 32 + lr + (sel >> 1) * 8;
    const int b_col = (sel & 1) * 16;

    float acc[4][4][4];
#pragma unroll
    for (int i = 0; i < 4; i++)
#pragma unroll
        for (int j = 0; j < 4; j++)
#pragma unroll
            for (int q = 0; q < 4; q++) acc[i][j][q] = 0.0f;

    // ---------------- prologue ----------------
    if (is_producer) {
        issue_chunk(0);
        issue_chunk(1);
        asm volatile("cp.async.wait_group 1;" ::: "memory");
        PROD_BAR();                 // all producers' chunk-0 groups retired
        convert_chunk(0);
    }
    __syncthreads();

    // ---------------- main loop (one block barrier per iter) ----------------
    for (int i = 0; i < NCHUNK; i++) {
        if (is_producer) {
            if (i + 2 < NCHUNK) issue_chunk(i + 2);
            if (i + 1 < NCHUNK) {
                if (i + 2 < NCHUNK) asm volatile("cp.async.wait_group 1;" ::: "memory");
                else                asm volatile("cp.async.wait_group 0;" ::: "memory");
                PROD_BAR();         // cross-thread cp.async visibility
                convert_chunk(i + 1);
            }
        } else {
            const uint32_t sA = sb + OFF_A(i % 3);
            const uint32_t sB = sb + OFF_B(i & 1);
#pragma unroll
            for (int ks = 0; ks < 2; ks++) {
                uint32_t af[4][4], bf[2][4];
                const uint32_t acol = ks * 32 + a_col;
                const uint32_t bcol = ks * 32 + b_col;
#pragma unroll
                for (int g = 0; g < 2; g++)
                    LDSM4(bf[g], sB + (uint32_t)(b_row + g * 16) * RS + bcol);
#pragma unroll
                for (int mf = 0; mf < 4; mf++)
                    LDSM4(af[mf], sA + (uint32_t)(a_row + mf * 16) * RS + acol);
#pragma unroll
                for (int mf = 0; mf < 4; mf++)
#pragma unroll
                    for (int nf = 0; nf < 4; nf++) {
                        const int g = nf >> 1, s2 = (nf & 1) * 2;
                        MMA_F16(acc[mf][nf], af[mf], bf[g][s2], bf[g][s2 + 1]);
                    }
            }
        }
        __syncthreads();
    }

    // ---------------- epilogue (consumers only) ----------------
    if (!is_producer && (t0 + warp_n * 32 < T_)) {
        const int mb = warp_m * 64 + (lane >> 2);
        const int cb = t0 + warp_n * 32 + (lane & 3) * 2;
#pragma unroll
        for (int mf = 0; mf < 4; mf++) {
#pragma unroll
            for (int nf = 0; nf < 4; nf++) {
                const int m = mb + mf * 16;
                const int t = cb + nf * 8;
                float* o0 = out + ((size_t)b * M_ + m) * T_ + t;
                float* o1 = out + ((size_t)b * M_ + m + 8) * T_ + t;
                *(float2*)o0 = make_float2(acc[mf][nf][0], acc[mf][nf][1]);
                *(float2*)o1 = make_float2(acc[mf][nf][2], acc[mf][nf][3]);
            }
        }
    }
}

// ---------------------------------------------------------------------------
extern "C" void kernel_launch(void* const* d_in, const int* in_sizes, int n_in,
                              void* d_out, int out_size) {
    const float* x    = (const float*)d_in[0];
    const float* pos  = (const float*)d_in[1];
    const float* tpos = (const float*)d_in[2];
    const float* w1   = (const float*)d_in[3];
    const float* b1   = (const float*)d_in[4];
    const float* w2   = (const float*)d_in[5];
    const float* b2   = (const float*)d_in[6];
    float* out = (float*)d_out;

    cudaFuncSetAttribute(mrm_hmma_kernel,
                         cudaFuncAttributeMaxDynamicSharedMemorySize, SMEM_TOTAL);

    mrm_weights_kernel<<<B_ * M_, CP_>>>(pos, tpos, w1, b1, w2, b2);

    dim3 grid((T_ + TN_ - 1) / TN_, B_);   // 32 x 16 = 512 CTAs
    mrm_hmma_kernel<<<grid, NTHREADS, SMEM_TOTAL>>>(x, out);
}